// round 10
// baseline (speedup 1.0000x reference)
#include <cuda_runtime.h>
#include <math.h>
#include <stdint.h>

#define NUM_E   8
#define DIM     1024
#define HID     4096
#define TOKENS  8192
#define CAP     TOKENS
#define ROWS_T  (TOKENS * 2)

// ------------------------------------------------------------- scratch
static __device__ float g_h[(size_t)ROWS_T * HID];              // 268 MB
static __device__ float g_y[(size_t)ROWS_T * DIM];              // 64 MB
static __device__ float g_W1t[(size_t)NUM_E * DIM * HID];       // 134 MB (tf32-rounded)
static __device__ float g_W2t[(size_t)NUM_E * HID * DIM];       // 134 MB (tf32-rounded)
static __device__ int   g_rowmap[NUM_E * CAP];
static __device__ int   g_cnt[NUM_E];
static __device__ float g_topw[ROWS_T];

// ------------------------------------------------------------- helpers
__device__ __forceinline__ uint32_t hi_bits(float f) {
    return __float_as_uint(f) & 0xFFFFE000u;   // exactly tf32-representable
}
__device__ __forceinline__ uint32_t cvt_tf32(float f) {
    uint32_t u;
    asm("cvt.rna.tf32.f32 %0, %1;" : "=r"(u) : "f"(f));
    return u;
}
__device__ __forceinline__ uint32_t lo_bits(float f) {
    return cvt_tf32(f - __uint_as_float(hi_bits(f)));
}
__device__ __forceinline__ float gelu_exact(float v) {
    return 0.5f * v * (1.0f + erff(v * 0.7071067811865476f));
}
__device__ __forceinline__ void mma_tf32(float* c, const uint32_t* a, const uint32_t* b) {
    asm volatile(
        "mma.sync.aligned.m16n8k8.row.col.f32.tf32.tf32.f32 "
        "{%0,%1,%2,%3}, {%4,%5,%6,%7}, {%8,%9}, {%0,%1,%2,%3};"
        : "+f"(c[0]), "+f"(c[1]), "+f"(c[2]), "+f"(c[3])
        : "r"(a[0]), "r"(a[1]), "r"(a[2]), "r"(a[3]), "r"(b[0]), "r"(b[1]));
}
__device__ __forceinline__ uint32_t smem_u32(const void* p) {
    uint32_t a;
    asm("{ .reg .u64 t; cvta.to.shared.u64 t, %1; cvt.u32.u64 %0, t; }" : "=r"(a) : "l"(p));
    return a;
}
#define CP_ASYNC16(saddr, gptr) \
    asm volatile("cp.async.cg.shared.global [%0], [%1], 16;" :: "r"(saddr), "l"(gptr))
#define CP_COMMIT() asm volatile("cp.async.commit_group;" ::: "memory")
#define CP_WAIT0()  asm volatile("cp.async.wait_group 0;" ::: "memory")

// ------------------------------------------------------------- router
__global__ void zero_cnt_kernel() {
    if (threadIdx.x < NUM_E) g_cnt[threadIdx.x] = 0;
}

__global__ __launch_bounds__(256) void router_kernel(
    const float* __restrict__ x, const float* __restrict__ Wr) {
    const int t = blockIdx.x;
    const int tid = threadIdx.x;
    const float4 xv = *(const float4*)(x + (size_t)t * DIM + tid * 4);
    float acc[NUM_E];
#pragma unroll
    for (int e = 0; e < NUM_E; e++) {
        const float4 wv = *(const float4*)(Wr + e * DIM + tid * 4);
        acc[e] = xv.x * wv.x + xv.y * wv.y + xv.z * wv.z + xv.w * wv.w;
    }
#pragma unroll
    for (int off = 16; off; off >>= 1)
#pragma unroll
        for (int e = 0; e < NUM_E; e++)
            acc[e] += __shfl_down_sync(0xffffffffu, acc[e], off);

    __shared__ float sred[8][NUM_E];
    const int wid = tid >> 5, lane = tid & 31;
    if (lane == 0)
#pragma unroll
        for (int e = 0; e < NUM_E; e++) sred[wid][e] = acc[e];
    __syncthreads();

    if (tid == 0) {
        float lg[NUM_E];
#pragma unroll
        for (int e = 0; e < NUM_E; e++) {
            float s = 0.f;
#pragma unroll
            for (int w = 0; w < 8; w++) s += sred[w][e];
            lg[e] = s;
        }
        float mx = lg[0];
#pragma unroll
        for (int e = 1; e < NUM_E; e++) mx = fmaxf(mx, lg[e]);
        float p[NUM_E], psum = 0.f;
#pragma unroll
        for (int e = 0; e < NUM_E; e++) { p[e] = expf(lg[e] - mx); psum += p[e]; }
        const float inv = 1.0f / psum;
#pragma unroll
        for (int e = 0; e < NUM_E; e++) p[e] *= inv;

        int i1 = 0;
#pragma unroll
        for (int e = 1; e < NUM_E; e++) if (p[e] > p[i1]) i1 = e;
        int i2 = -1;
#pragma unroll
        for (int e = 0; e < NUM_E; e++) {
            if (e == i1) continue;
            if (i2 < 0 || p[e] > p[i2]) i2 = e;
        }
        int p1 = atomicAdd(&g_cnt[i1], 1);
        g_rowmap[i1 * CAP + p1] = t * 2;
        int p2 = atomicAdd(&g_cnt[i2], 1);
        g_rowmap[i2 * CAP + p2] = t * 2 + 1;
        g_topw[t * 2]     = p[i1];
        g_topw[t * 2 + 1] = p[i2];
    }
}

// ------------------------------------------------------------- W round (fp32 -> tf32, rna)
__global__ __launch_bounds__(256) void round_w1_kernel(const float* __restrict__ src) {
    const int i = blockIdx.x * 256 + threadIdx.x;
    const float4 v = ((const float4*)src)[i];
    uint4 r;
    r.x = cvt_tf32(v.x); r.y = cvt_tf32(v.y);
    r.z = cvt_tf32(v.z); r.w = cvt_tf32(v.w);
    ((uint4*)g_W1t)[i] = r;
}
__global__ __launch_bounds__(256) void round_w2_kernel(const float* __restrict__ src) {
    const int i = blockIdx.x * 256 + threadIdx.x;
    const float4 v = ((const float4*)src)[i];
    uint4 r;
    r.x = cvt_tf32(v.x); r.y = cvt_tf32(v.y);
    r.z = cvt_tf32(v.z); r.w = cvt_tf32(v.w);
    ((uint4*)g_W2t)[i] = r;
}

// ------------------------------------------------------------- mma.sync grouped GEMM
// block 128x256, BK=16; 8 warps of 64x64; 2-term split (ah*b + al*b),
// B pre-rounded tf32 loaded via cp.async; A LDG->hi/lo STS.
#define BM 128
#define BN 256
#define BK 16
#define SA_PITCH 20                      // (20*lr+lc) mod 32 all distinct
#define SB_PITCH 264                     // 264 mod 32 = 8 -> (8*lc+lr) distinct
#define A_WORDS (BM * SA_PITCH)          // 2560 per tile (hi + lo = 5120)
#define AB_WORDS (2 * A_WORDS)           // 5120
#define B_WORDS (BK * SB_PITCH)          // 4224
#define STAGE_WORDS (AB_WORDS + B_WORDS) // 9344
#define SMEM_GEMM (2 * STAGE_WORDS * 4)  // 74752 bytes (needs opt-in)

template <int KDIM, int NDIM, bool DO_GELU, bool GATHER>
__device__ __forceinline__ void gemm_mma_body(
    const float* __restrict__ A, const float* __restrict__ Bt,
    const float* __restrict__ bias, float* __restrict__ Cout) {
    extern __shared__ uint32_t smem[];
    const int e = blockIdx.z;
    const int cnt = g_cnt[e];
    const int m0 = blockIdx.x * BM;
    if (m0 >= cnt) return;
    const int n0 = blockIdx.y * BN;
    const int tid = threadIdx.x;
    const int wid = tid >> 5, lane = tid & 31;
    const int wm = wid & 1, wn = wid >> 1;          // warp tile (wm*64, wn*64)
    const int lr = lane >> 2, lc = lane & 3;

    // ---- A loader: thread -> (row am, half ah): 8 floats (2 float4)
    const int am = tid & 127, ah = tid >> 7;
    const int gm = m0 + am;
    const int rA = g_rowmap[e * CAP + (gm < cnt ? gm : 0)];
    const float* pa = A + (size_t)(GATHER ? (rA >> 1) : rA) * KDIM + ah * 8;
    const uint32_t offAh = am * SA_PITCH + ah * 8;      // + A_WORDS for lo tile

    // ---- B loader (cp.async): thread -> (k-row bk, col bc), 4 x 16B
    const int bk = tid >> 4, bc = (tid & 15) * 4;
    const uint32_t smem_b_u32 = smem_u32(smem) + (AB_WORDS + bk * SB_PITCH + bc) * 4;
    const float* pb = Bt + (size_t)e * KDIM * NDIM + (size_t)bk * NDIM + n0 + bc;

    const int KB = KDIM / BK;

    float c[4][8][4];
#pragma unroll
    for (int mt = 0; mt < 4; mt++)
#pragma unroll
        for (int nt = 0; nt < 8; nt++)
#pragma unroll
            for (int j = 0; j < 4; j++) c[mt][nt][j] = 0.f;

    // ---- preload epoch 0: B via cp.async into buf0, A into regs
    float4 av0 = *(const float4*)(pa);
    float4 av1 = *(const float4*)(pa + 4);
#pragma unroll
    for (int j = 0; j < 4; j++)
        CP_ASYNC16(smem_b_u32 + j * 256, pb + j * 64);
    CP_COMMIT();

    for (int kb = 0; kb < KB; kb++) {
        const int buf = kb & 1;
        uint32_t* sbase = smem + buf * STAGE_WORDS;

        // ---- STS A: hi tile + lo tile (one LDG worth -> four uint4 STS)
        {
            uint4 h0, h1, l0, l1;
            h0.x = hi_bits(av0.x); h0.y = hi_bits(av0.y);
            h0.z = hi_bits(av0.z); h0.w = hi_bits(av0.w);
            h1.x = hi_bits(av1.x); h1.y = hi_bits(av1.y);
            h1.z = hi_bits(av1.z); h1.w = hi_bits(av1.w);
            l0.x = lo_bits(av0.x); l0.y = lo_bits(av0.y);
            l0.z = lo_bits(av0.z); l0.w = lo_bits(av0.w);
            l1.x = lo_bits(av1.x); l1.y = lo_bits(av1.y);
            l1.z = lo_bits(av1.z); l1.w = lo_bits(av1.w);
            *(uint4*)(sbase + offAh)               = h0;
            *(uint4*)(sbase + offAh + 4)           = h1;
            *(uint4*)(sbase + offAh + A_WORDS)     = l0;
            *(uint4*)(sbase + offAh + A_WORDS + 4) = l1;
        }
        CP_WAIT0();            // B for this buf has landed
        __syncthreads();       // A STS visible; prior reads of buf^1 done

        // ---- issue next epoch loads (fully overlapped with 128 MMAs below)
        if (kb + 1 < KB) {
            const float* pan = pa + (kb + 1) * BK;
            av0 = *(const float4*)(pan);
            av1 = *(const float4*)(pan + 4);
            const float* pbn = pb + (size_t)(kb + 1) * BK * NDIM;
            const uint32_t sdst = smem_b_u32 + (buf ^ 1) * (STAGE_WORDS * 4);
#pragma unroll
            for (int j = 0; j < 4; j++)
                CP_ASYNC16(sdst + j * 256, pbn + j * 64);
            CP_COMMIT();
        }

        // ---- compute: 2 k8-steps x 2 passes x 32 MMAs
        const uint32_t* st = smem + buf * STAGE_WORDS;
        const uint32_t* sB = st + AB_WORDS;
#pragma unroll
        for (int ks = 0; ks < 2; ks++) {
            uint32_t b[8][2];
#pragma unroll
            for (int nt = 0; nt < 8; nt++) {
                const uint32_t* p = sB + (ks * 8 + lc) * SB_PITCH + wn * 64 + nt * 8 + lr;
                b[nt][0] = p[0];
                b[nt][1] = p[4 * SB_PITCH];
            }
#pragma unroll
            for (int pass = 0; pass < 2; pass++) {
                const uint32_t* sA = st + pass * A_WORDS;
                uint32_t a[4][4];
#pragma unroll
                for (int mt = 0; mt < 4; mt++) {
                    const uint32_t* p = sA + (wm * 64 + mt * 16 + lr) * SA_PITCH + ks * 8 + lc;
                    a[mt][0] = p[0];
                    a[mt][1] = p[8 * SA_PITCH];
                    a[mt][2] = p[4];
                    a[mt][3] = p[8 * SA_PITCH + 4];
                }
#pragma unroll
                for (int mt = 0; mt < 4; mt++)
#pragma unroll
                    for (int nt = 0; nt < 8; nt++)
                        mma_tf32(c[mt][nt], a[mt], b[nt]);
            }
        }
    }

    // ---- epilogue: bias (+GELU) + rowmap scatter
    const int lc2 = (lane & 3) * 2;
    const float* pbias = bias + (size_t)e * NDIM + n0 + wn * 64;
    float2 bv[8];
#pragma unroll
    for (int nt = 0; nt < 8; nt++)
        bv[nt] = *(const float2*)(pbias + nt * 8 + lc2);

#pragma unroll
    for (int mt = 0; mt < 4; mt++) {
#pragma unroll
        for (int half = 0; half < 2; half++) {
            const int gmr = m0 + wm * 64 + mt * 16 + half * 8 + lr;
            if (gmr >= cnt) continue;
            const int r = g_rowmap[e * CAP + gmr];
            float* pr = Cout + (size_t)r * NDIM + n0 + wn * 64;
#pragma unroll
            for (int nt = 0; nt < 8; nt++) {
                float x0 = c[mt][nt][half * 2 + 0] + bv[nt].x;
                float x1 = c[mt][nt][half * 2 + 1] + bv[nt].y;
                if (DO_GELU) { x0 = gelu_exact(x0); x1 = gelu_exact(x1); }
                *(float2*)(pr + nt * 8 + lc2) = make_float2(x0, x1);
            }
        }
    }
}

__global__ __launch_bounds__(256, 1) void fc1_mma_kernel(
    const float* __restrict__ x, const float* __restrict__ b1) {
    gemm_mma_body<DIM, HID, true, true>(x, g_W1t, b1, g_h);
}
__global__ __launch_bounds__(256, 1) void fc2_mma_kernel(const float* __restrict__ b2) {
    gemm_mma_body<HID, DIM, false, false>(g_h, g_W2t, b2, g_y);
}

// ------------------------------------------------------------- combine
__global__ __launch_bounds__(256) void combine_kernel(float* __restrict__ out) {
    const int t = blockIdx.x;
    const int d = threadIdx.x * 4;
    const float w0 = g_topw[2 * t];
    const float w1 = g_topw[2 * t + 1];
    const float4 y0 = *(const float4*)&g_y[(size_t)(2 * t) * DIM + d];
    const float4 y1 = *(const float4*)&g_y[(size_t)(2 * t + 1) * DIM + d];
    float4 o;
    o.x = w0 * y0.x + w1 * y1.x;
    o.y = w0 * y0.y + w1 * y1.y;
    o.z = w0 * y0.z + w1 * y1.z;
    o.w = w0 * y0.w + w1 * y1.w;
    *(float4*)(out + (size_t)t * DIM + d) = o;
}

// ------------------------------------------------------------- launch
extern "C" void kernel_launch(void* const* d_in, const int* in_sizes, int n_in,
                              void* d_out, int out_size) {
    const float* x  = (const float*)d_in[0];
    const float* Wr = (const float*)d_in[1];
    const float* W1 = (const float*)d_in[2];
    const float* b1 = (const float*)d_in[3];
    const float* W2 = (const float*)d_in[4];
    const float* b2 = (const float*)d_in[5];
    float* out = (float*)d_out;
    (void)in_sizes; (void)n_in; (void)out_size;

    // Unconditional (no static guard): host-side attribute set, capture-safe.
    cudaFuncSetAttribute(fc1_mma_kernel,
                         cudaFuncAttributeMaxDynamicSharedMemorySize, SMEM_GEMM);
    cudaFuncSetAttribute(fc2_mma_kernel,
                         cudaFuncAttributeMaxDynamicSharedMemorySize, SMEM_GEMM);

    zero_cnt_kernel<<<1, 32>>>();
    router_kernel<<<TOKENS, 256>>>(x, Wr);
    round_w1_kernel<<<NUM_E * DIM * HID / 4 / 256, 256>>>(W1);
    round_w2_kernel<<<NUM_E * HID * DIM / 4 / 256, 256>>>(W2);
    fc1_mma_kernel<<<dim3(CAP / BM, HID / BN, NUM_E), 256, SMEM_GEMM>>>(x, b1);
    fc2_mma_kernel<<<dim3(CAP / BM, DIM / BN, NUM_E), 256, SMEM_GEMM>>>(b2);
    combine_kernel<<<TOKENS, 256>>>(out);
}

// round 11
// speedup vs baseline: 1.5605x; 1.5605x over previous
#include <cuda_runtime.h>
#include <math.h>
#include <stdint.h>

#define NUM_E   8
#define DIM     1024
#define HID     4096
#define TOKENS  8192
#define CAP     TOKENS
#define ROWS_T  (TOKENS * 2)

// ------------------------------------------------------------- scratch
static __device__ float g_h[(size_t)ROWS_T * HID];              // 268 MB
static __device__ float g_y[(size_t)ROWS_T * DIM];              // 64 MB
static __device__ float g_W1t[(size_t)NUM_E * DIM * HID];       // 134 MB (tf32-rounded)
static __device__ float g_W2t[(size_t)NUM_E * HID * DIM];       // 134 MB (tf32-rounded)
static __device__ int   g_rowmap[NUM_E * CAP];
static __device__ int   g_cnt[NUM_E];
static __device__ float g_topw[ROWS_T];

// ------------------------------------------------------------- helpers
__device__ __forceinline__ uint32_t hi_bits(float f) {
    return __float_as_uint(f) & 0xFFFFE000u;   // exactly tf32-representable
}
__device__ __forceinline__ uint32_t cvt_tf32(float f) {
    uint32_t u;
    asm("cvt.rna.tf32.f32 %0, %1;" : "=r"(u) : "f"(f));
    return u;
}
__device__ __forceinline__ uint32_t lo_bits(float f) {
    return cvt_tf32(f - __uint_as_float(hi_bits(f)));
}
__device__ __forceinline__ float gelu_exact(float v) {
    return 0.5f * v * (1.0f + erff(v * 0.7071067811865476f));
}
__device__ __forceinline__ void mma_tf32(float* c, const uint32_t* a, const uint32_t* b) {
    asm volatile(
        "mma.sync.aligned.m16n8k8.row.col.f32.tf32.tf32.f32 "
        "{%0,%1,%2,%3}, {%4,%5,%6,%7}, {%8,%9}, {%0,%1,%2,%3};"
        : "+f"(c[0]), "+f"(c[1]), "+f"(c[2]), "+f"(c[3])
        : "r"(a[0]), "r"(a[1]), "r"(a[2]), "r"(a[3]), "r"(b[0]), "r"(b[1]));
}

// ------------------------------------------------------------- router
__global__ void zero_cnt_kernel() {
    if (threadIdx.x < NUM_E) g_cnt[threadIdx.x] = 0;
}

__global__ __launch_bounds__(256) void router_kernel(
    const float* __restrict__ x, const float* __restrict__ Wr) {
    const int t = blockIdx.x;
    const int tid = threadIdx.x;
    const float4 xv = *(const float4*)(x + (size_t)t * DIM + tid * 4);
    float acc[NUM_E];
#pragma unroll
    for (int e = 0; e < NUM_E; e++) {
        const float4 wv = *(const float4*)(Wr + e * DIM + tid * 4);
        acc[e] = xv.x * wv.x + xv.y * wv.y + xv.z * wv.z + xv.w * wv.w;
    }
#pragma unroll
    for (int off = 16; off; off >>= 1)
#pragma unroll
        for (int e = 0; e < NUM_E; e++)
            acc[e] += __shfl_down_sync(0xffffffffu, acc[e], off);

    __shared__ float sred[8][NUM_E];
    const int wid = tid >> 5, lane = tid & 31;
    if (lane == 0)
#pragma unroll
        for (int e = 0; e < NUM_E; e++) sred[wid][e] = acc[e];
    __syncthreads();

    if (tid == 0) {
        float lg[NUM_E];
#pragma unroll
        for (int e = 0; e < NUM_E; e++) {
            float s = 0.f;
#pragma unroll
            for (int w = 0; w < 8; w++) s += sred[w][e];
            lg[e] = s;
        }
        float mx = lg[0];
#pragma unroll
        for (int e = 1; e < NUM_E; e++) mx = fmaxf(mx, lg[e]);
        float p[NUM_E], psum = 0.f;
#pragma unroll
        for (int e = 0; e < NUM_E; e++) { p[e] = expf(lg[e] - mx); psum += p[e]; }
        const float inv = 1.0f / psum;
#pragma unroll
        for (int e = 0; e < NUM_E; e++) p[e] *= inv;

        int i1 = 0;
#pragma unroll
        for (int e = 1; e < NUM_E; e++) if (p[e] > p[i1]) i1 = e;
        int i2 = -1;
#pragma unroll
        for (int e = 0; e < NUM_E; e++) {
            if (e == i1) continue;
            if (i2 < 0 || p[e] > p[i2]) i2 = e;
        }
        int p1 = atomicAdd(&g_cnt[i1], 1);
        g_rowmap[i1 * CAP + p1] = t * 2;
        int p2 = atomicAdd(&g_cnt[i2], 1);
        g_rowmap[i2 * CAP + p2] = t * 2 + 1;
        g_topw[t * 2]     = p[i1];
        g_topw[t * 2 + 1] = p[i2];
    }
}

// ------------------------------------------------------------- W round (fp32 -> tf32, rna)
__global__ __launch_bounds__(256) void round_w1_kernel(const float* __restrict__ src) {
    const int i = blockIdx.x * 256 + threadIdx.x;
    const float4 v = ((const float4*)src)[i];
    uint4 r;
    r.x = cvt_tf32(v.x); r.y = cvt_tf32(v.y);
    r.z = cvt_tf32(v.z); r.w = cvt_tf32(v.w);
    ((uint4*)g_W1t)[i] = r;
}
__global__ __launch_bounds__(256) void round_w2_kernel(const float* __restrict__ src) {
    const int i = blockIdx.x * 256 + threadIdx.x;
    const float4 v = ((const float4*)src)[i];
    uint4 r;
    r.x = cvt_tf32(v.x); r.y = cvt_tf32(v.y);
    r.z = cvt_tf32(v.z); r.w = cvt_tf32(v.w);
    ((uint4*)g_W2t)[i] = r;
}

// ------------------------------------------------------------- mma.sync grouped GEMM
// block 128x128, BK=8; 8 warps of 64x32; 2-term split (ah*b + al*b);
// 33 KB smem, <=128 regs -> 2 CTAs/SM for cross-CTA latency hiding.
#define BM 128
#define BN 128
#define BK 8
#define SA_PITCH 12                      // (12*lr+lc) mod 32 all distinct
#define SB_PITCH 136                     // 136 mod 32 = 8 -> (8*lc+lr) distinct
#define A_WORDS (BM * SA_PITCH)          // 1536 per tile (hi + lo = 3072)
#define B_WORDS (BK * SB_PITCH)          // 1088
#define STAGE_WORDS (2 * A_WORDS + B_WORDS)   // 4160
#define SMEM_GEMM (2 * STAGE_WORDS * 4)       // 33280 bytes (< 48 KB)

template <int KDIM, int NDIM, bool DO_GELU, bool GATHER>
__device__ __forceinline__ void gemm_mma_body(
    const float* __restrict__ A, const float* __restrict__ Bt,
    const float* __restrict__ bias, float* __restrict__ Cout) {
    extern __shared__ uint32_t smem[];
    const int e = blockIdx.z;
    const int cnt = g_cnt[e];
    const int m0 = blockIdx.x * BM;
    if (m0 >= cnt) return;
    const int n0 = blockIdx.y * BN;
    const int tid = threadIdx.x;
    const int wid = tid >> 5, lane = tid & 31;
    const int wm = wid & 1, wn = wid >> 1;          // warp tile (wm*64, wn*32)
    const int lr = lane >> 2, lc = lane & 3;

    // ---- A loader: 2 threads per row, 4 floats each
    const int am = tid >> 1, ah = tid & 1;
    const int gm = m0 + am;
    const int rA = g_rowmap[e * CAP + (gm < cnt ? gm : 0)];
    const float* pa = A + (size_t)(GATHER ? (rA >> 1) : rA) * KDIM + ah * 4;
    const uint32_t offAh = am * SA_PITCH + ah * 4;      // + A_WORDS for lo tile

    // ---- B loader: 32 threads per k-row, one float4 each
    const int bk = tid >> 5, bc = (tid & 31) * 4;
    const uint32_t offB = 2 * A_WORDS + bk * SB_PITCH + bc;
    const float* pb = Bt + (size_t)e * KDIM * NDIM + (size_t)bk * NDIM + n0 + bc;

    const int KB = KDIM / BK;

    float c[4][4][4];
#pragma unroll
    for (int mt = 0; mt < 4; mt++)
#pragma unroll
        for (int nt = 0; nt < 4; nt++)
#pragma unroll
            for (int j = 0; j < 4; j++) c[mt][nt][j] = 0.f;

    // ---- prefetch epoch 0
    float4 av = *(const float4*)(pa);
    float4 bv = *(const float4*)(pb);

    for (int kb = 0; kb < KB; kb++) {
        const int buf = kb & 1;
        uint32_t* sbase = smem + buf * STAGE_WORDS;

        // ---- STS: A split hi+lo (one LDG -> two STS); B raw tf32
        {
            uint4 hh, ll;
            hh.x = hi_bits(av.x); hh.y = hi_bits(av.y);
            hh.z = hi_bits(av.z); hh.w = hi_bits(av.w);
            ll.x = lo_bits(av.x); ll.y = lo_bits(av.y);
            ll.z = lo_bits(av.z); ll.w = lo_bits(av.w);
            *(uint4*)(sbase + offAh)           = hh;
            *(uint4*)(sbase + offAh + A_WORDS) = ll;
            *(float4*)(sbase + offB)           = bv;
        }
        __syncthreads();

        // ---- prefetch next epoch (overlaps compute below)
        if (kb + 1 < KB) {
            av = *(const float4*)(pa + (kb + 1) * BK);
            bv = *(const float4*)(pb + (size_t)(kb + 1) * BK * NDIM);
        }

        // ---- compute: b-frags loaded once, reused across both passes
        const uint32_t* st = smem + buf * STAGE_WORDS;
        const uint32_t* sB = st + 2 * A_WORDS;
        uint32_t b[4][2];
#pragma unroll
        for (int nt = 0; nt < 4; nt++) {
            const uint32_t* p = sB + lc * SB_PITCH + wn * 32 + nt * 8 + lr;
            b[nt][0] = p[0];
            b[nt][1] = p[4 * SB_PITCH];
        }
#pragma unroll
        for (int pass = 0; pass < 2; pass++) {
            const uint32_t* sA = st + pass * A_WORDS;
            uint32_t a[4][4];
#pragma unroll
            for (int mt = 0; mt < 4; mt++) {
                const uint32_t* p = sA + (wm * 64 + mt * 16 + lr) * SA_PITCH + lc;
                a[mt][0] = p[0];
                a[mt][1] = p[8 * SA_PITCH];
                a[mt][2] = p[4];
                a[mt][3] = p[8 * SA_PITCH + 4];
            }
#pragma unroll
            for (int mt = 0; mt < 4; mt++)
#pragma unroll
                for (int nt = 0; nt < 4; nt++)
                    mma_tf32(c[mt][nt], a[mt], b[nt]);
        }
    }

    // ---- epilogue: bias (+GELU) + rowmap scatter
    const int lc2 = (lane & 3) * 2;
    const float* pbias = bias + (size_t)e * NDIM + n0 + wn * 32;
    float2 bv2[4];
#pragma unroll
    for (int nt = 0; nt < 4; nt++)
        bv2[nt] = *(const float2*)(pbias + nt * 8 + lc2);

#pragma unroll
    for (int mt = 0; mt < 4; mt++) {
#pragma unroll
        for (int half = 0; half < 2; half++) {
            const int gmr = m0 + wm * 64 + mt * 16 + half * 8 + lr;
            if (gmr >= cnt) continue;
            const int r = g_rowmap[e * CAP + gmr];
            float* pr = Cout + (size_t)r * NDIM + n0 + wn * 32;
#pragma unroll
            for (int nt = 0; nt < 4; nt++) {
                float x0 = c[mt][nt][half * 2 + 0] + bv2[nt].x;
                float x1 = c[mt][nt][half * 2 + 1] + bv2[nt].y;
                if (DO_GELU) { x0 = gelu_exact(x0); x1 = gelu_exact(x1); }
                *(float2*)(pr + nt * 8 + lc2) = make_float2(x0, x1);
            }
        }
    }
}

__global__ __launch_bounds__(256, 2) void fc1_mma_kernel(
    const float* __restrict__ x, const float* __restrict__ b1) {
    gemm_mma_body<DIM, HID, true, true>(x, g_W1t, b1, g_h);
}
__global__ __launch_bounds__(256, 2) void fc2_mma_kernel(const float* __restrict__ b2) {
    gemm_mma_body<HID, DIM, false, false>(g_h, g_W2t, b2, g_y);
}

// ------------------------------------------------------------- combine
__global__ __launch_bounds__(256) void combine_kernel(float* __restrict__ out) {
    const int t = blockIdx.x;
    const int d = threadIdx.x * 4;
    const float w0 = g_topw[2 * t];
    const float w1 = g_topw[2 * t + 1];
    const float4 y0 = *(const float4*)&g_y[(size_t)(2 * t) * DIM + d];
    const float4 y1 = *(const float4*)&g_y[(size_t)(2 * t + 1) * DIM + d];
    float4 o;
    o.x = w0 * y0.x + w1 * y1.x;
    o.y = w0 * y0.y + w1 * y1.y;
    o.z = w0 * y0.z + w1 * y1.z;
    o.w = w0 * y0.w + w1 * y1.w;
    *(float4*)(out + (size_t)t * DIM + d) = o;
}

// ------------------------------------------------------------- launch
extern "C" void kernel_launch(void* const* d_in, const int* in_sizes, int n_in,
                              void* d_out, int out_size) {
    const float* x  = (const float*)d_in[0];
    const float* Wr = (const float*)d_in[1];
    const float* W1 = (const float*)d_in[2];
    const float* b1 = (const float*)d_in[3];
    const float* W2 = (const float*)d_in[4];
    const float* b2 = (const float*)d_in[5];
    float* out = (float*)d_out;
    (void)in_sizes; (void)n_in; (void)out_size;

    zero_cnt_kernel<<<1, 32>>>();
    router_kernel<<<TOKENS, 256>>>(x, Wr);
    round_w1_kernel<<<NUM_E * DIM * HID / 4 / 256, 256>>>(W1);
    round_w2_kernel<<<NUM_E * HID * DIM / 4 / 256, 256>>>(W2);
    fc1_mma_kernel<<<dim3(CAP / BM, HID / BN, NUM_E), 256, SMEM_GEMM>>>(x, b1);
    fc2_mma_kernel<<<dim3(CAP / BM, DIM / BN, NUM_E), 256, SMEM_GEMM>>>(b2);
    combine_kernel<<<TOKENS, 256>>>(out);
}

// round 14
// speedup vs baseline: 2.1622x; 1.3856x over previous
#include <cuda_runtime.h>
#include <cuda_bf16.h>
#include <math.h>
#include <stdint.h>

#define NUM_E   8
#define DIM     1024
#define HID     4096
#define TOKENS  8192
#define CAP     TOKENS
#define ROWS_T  (TOKENS * 2)

// ------------------------------------------------------------- scratch
static __device__ float    g_h[(size_t)ROWS_T * HID];                 // 268 MB
static __device__ float    g_y[(size_t)ROWS_T * DIM];                 // 64 MB
static __device__ uint32_t g_W1h[(size_t)NUM_E * (DIM / 2) * HID];    // 67 MB (bf16x2 kpair)
static __device__ uint32_t g_W1l[(size_t)NUM_E * (DIM / 2) * HID];    // 67 MB
static __device__ uint32_t g_W2h[(size_t)NUM_E * (HID / 2) * DIM];    // 67 MB
static __device__ uint32_t g_W2l[(size_t)NUM_E * (HID / 2) * DIM];    // 67 MB
static __device__ int      g_rowmap[NUM_E * CAP];
static __device__ int      g_cnt[NUM_E];
static __device__ float    g_topw[ROWS_T];

// ------------------------------------------------------------- helpers
__device__ __forceinline__ float gelu_exact(float v) {
    return 0.5f * v * (1.0f + erff(v * 0.7071067811865476f));
}
// pack two floats (even-k first) to bf16x2; return residuals
__device__ __forceinline__ uint32_t pack_hi(float a, float b, float& ra, float& rb) {
    __nv_bfloat162 p = __floats2bfloat162_rn(a, b);
    ra = a - __bfloat162float(p.x);
    rb = b - __bfloat162float(p.y);
    return *(uint32_t*)&p;
}
__device__ __forceinline__ uint32_t pack_bf2(float a, float b) {
    __nv_bfloat162 p = __floats2bfloat162_rn(a, b);
    return *(uint32_t*)&p;
}
__device__ __forceinline__ void mma_bf16(float* c, const uint32_t* a, const uint32_t* b) {
    asm volatile(
        "mma.sync.aligned.m16n8k16.row.col.f32.bf16.bf16.f32 "
        "{%0,%1,%2,%3}, {%4,%5,%6,%7}, {%8,%9}, {%0,%1,%2,%3};"
        : "+f"(c[0]), "+f"(c[1]), "+f"(c[2]), "+f"(c[3])
        : "r"(a[0]), "r"(a[1]), "r"(a[2]), "r"(a[3]), "r"(b[0]), "r"(b[1]));
}

// ------------------------------------------------------------- router
__global__ void zero_cnt_kernel() {
    if (threadIdx.x < NUM_E) g_cnt[threadIdx.x] = 0;
}

__global__ __launch_bounds__(256) void router_kernel(
    const float* __restrict__ x, const float* __restrict__ Wr) {
    const int t = blockIdx.x;
    const int tid = threadIdx.x;
    const float4 xv = *(const float4*)(x + (size_t)t * DIM + tid * 4);
    float acc[NUM_E];
#pragma unroll
    for (int e = 0; e < NUM_E; e++) {
        const float4 wv = *(const float4*)(Wr + e * DIM + tid * 4);
        acc[e] = xv.x * wv.x + xv.y * wv.y + xv.z * wv.z + xv.w * wv.w;
    }
#pragma unroll
    for (int off = 16; off; off >>= 1)
#pragma unroll
        for (int e = 0; e < NUM_E; e++)
            acc[e] += __shfl_down_sync(0xffffffffu, acc[e], off);

    __shared__ float sred[8][NUM_E];
    const int wid = tid >> 5, lane = tid & 31;
    if (lane == 0)
#pragma unroll
        for (int e = 0; e < NUM_E; e++) sred[wid][e] = acc[e];
    __syncthreads();

    if (tid == 0) {
        float lg[NUM_E];
#pragma unroll
        for (int e = 0; e < NUM_E; e++) {
            float s = 0.f;
#pragma unroll
            for (int w = 0; w < 8; w++) s += sred[w][e];
            lg[e] = s;
        }
        float mx = lg[0];
#pragma unroll
        for (int e = 1; e < NUM_E; e++) mx = fmaxf(mx, lg[e]);
        float p[NUM_E], psum = 0.f;
#pragma unroll
        for (int e = 0; e < NUM_E; e++) { p[e] = expf(lg[e] - mx); psum += p[e]; }
        const float inv = 1.0f / psum;
#pragma unroll
        for (int e = 0; e < NUM_E; e++) p[e] *= inv;

        int i1 = 0;
#pragma unroll
        for (int e = 1; e < NUM_E; e++) if (p[e] > p[i1]) i1 = e;
        int i2 = -1;
#pragma unroll
        for (int e = 0; e < NUM_E; e++) {
            if (e == i1) continue;
            if (i2 < 0 || p[e] > p[i2]) i2 = e;
        }
        int p1 = atomicAdd(&g_cnt[i1], 1);
        g_rowmap[i1 * CAP + p1] = t * 2;
        int p2 = atomicAdd(&g_cnt[i2], 1);
        g_rowmap[i2 * CAP + p2] = t * 2 + 1;
        g_topw[t * 2]     = p[i1];
        g_topw[t * 2 + 1] = p[i2];
    }
}

// ------------------------------------------------------------- W split (fp32 -> packed bf16 hi/lo)
// Word layout: [e][kpair][n], word = (bf16 W[2kp][n] low, bf16 W[2kp+1][n] high)
__global__ __launch_bounds__(256) void split_w1_kernel(const float* __restrict__ src) {
    const int i = blockIdx.x * 256 + threadIdx.x;       // (e, kp, n4)
    const int n  = (i & (HID / 4 - 1)) * 4;
    const int t  = i / (HID / 4);
    const int kp = t & (DIM / 2 - 1);
    const int e  = t / (DIM / 2);
    const float* s0 = src + ((size_t)e * DIM + 2 * kp) * HID + n;
    const float4 v0 = *(const float4*)s0;
    const float4 v1 = *(const float4*)(s0 + HID);
    uint4 h, l;
    float ra, rb;
    h.x = pack_hi(v0.x, v1.x, ra, rb); l.x = pack_bf2(ra, rb);
    h.y = pack_hi(v0.y, v1.y, ra, rb); l.y = pack_bf2(ra, rb);
    h.z = pack_hi(v0.z, v1.z, ra, rb); l.z = pack_bf2(ra, rb);
    h.w = pack_hi(v0.w, v1.w, ra, rb); l.w = pack_bf2(ra, rb);
    ((uint4*)g_W1h)[i] = h;
    ((uint4*)g_W1l)[i] = l;
}
__global__ __launch_bounds__(256) void split_w2_kernel(const float* __restrict__ src) {
    const int i = blockIdx.x * 256 + threadIdx.x;
    const int n  = (i & (DIM / 4 - 1)) * 4;
    const int t  = i / (DIM / 4);
    const int kp = t & (HID / 2 - 1);
    const int e  = t / (HID / 2);
    const float* s0 = src + ((size_t)e * HID + 2 * kp) * DIM + n;
    const float4 v0 = *(const float4*)s0;
    const float4 v1 = *(const float4*)(s0 + DIM);
    uint4 h, l;
    float ra, rb;
    h.x = pack_hi(v0.x, v1.x, ra, rb); l.x = pack_bf2(ra, rb);
    h.y = pack_hi(v0.y, v1.y, ra, rb); l.y = pack_bf2(ra, rb);
    h.z = pack_hi(v0.z, v1.z, ra, rb); l.z = pack_bf2(ra, rb);
    h.w = pack_hi(v0.w, v1.w, ra, rb); l.w = pack_bf2(ra, rb);
    ((uint4*)g_W2h)[i] = h;
    ((uint4*)g_W2l)[i] = l;
}

// ------------------------------------------------------------- bf16 mma grouped GEMM
// block 128x128, BK=16 (8 kpair words); 8 warps of 64x32;
// 3-term split: Ah*Bh + Ah*Bl + Al*Bh (fp32 accum).
#define BM 128
#define BN 128
#define BK 16
#define SA_PITCH 12                        // words/row (8 kpairs + pad 4)
#define SB_PITCH 136                       // words/kpair-row (128 cols + pad 8)
#define A_WORDS (BM * SA_PITCH)            // 1536 per tile (Ah + Al = 3072)
#define B_WORDS (8 * SB_PITCH)             // 1088 per tile (Bh + Bl = 2176)
#define STAGE_WORDS (2 * A_WORDS + 2 * B_WORDS)   // 5248
#define SMEM_GEMM (2 * STAGE_WORDS * 4)           // 41984 bytes (< 48 KB)

template <int KDIM, int NDIM, bool DO_GELU, bool GATHER>
__device__ __forceinline__ void gemm_mma_body(
    const float* __restrict__ A, const uint32_t* __restrict__ Bh,
    const uint32_t* __restrict__ Bl, const float* __restrict__ bias,
    float* __restrict__ Cout) {
    extern __shared__ uint32_t smem[];
    const int e = blockIdx.z;
    const int cnt = g_cnt[e];
    const int m0 = blockIdx.x * BM;
    if (m0 >= cnt) return;
    const int n0 = blockIdx.y * BN;
    const int tid = threadIdx.x;
    const int wid = tid >> 5, lane = tid & 31;
    const int wm = wid & 1, wn = wid >> 1;          // warp tile (wm*64, wn*32)
    const int lr = lane >> 2, lc = lane & 3;

    // ---- A loader: 2 threads per row, 8 floats (-> 4 kpair words) each
    const int am = tid >> 1, ah = tid & 1;
    const int gm = m0 + am;
    const int rA = g_rowmap[e * CAP + (gm < cnt ? gm : 0)];
    const float* pa = A + (size_t)(GATHER ? (rA >> 1) : rA) * KDIM + ah * 8;
    const uint32_t offA = am * SA_PITCH + ah * 4;       // +A_WORDS for lo tile

    // ---- B loader: 32 threads per kpair-row, one uint4 from each of Bh/Bl
    const int bkr = tid >> 5, bc4 = (tid & 31) * 4;
    const uint32_t offBh = 2 * A_WORDS + bkr * SB_PITCH + bc4;
    const size_t b_off = ((size_t)e * (KDIM / 2) + bkr) * NDIM + n0 + bc4;

    const int KB = KDIM / BK;

    float c[4][4][4];
#pragma unroll
    for (int mt = 0; mt < 4; mt++)
#pragma unroll
        for (int nt = 0; nt < 4; nt++)
#pragma unroll
            for (int j = 0; j < 4; j++) c[mt][nt][j] = 0.f;

    // ---- prefetch epoch 0
    float4 u0 = *(const float4*)(pa);
    float4 u1 = *(const float4*)(pa + 4);
    uint4 wh = *(const uint4*)(Bh + b_off);
    uint4 wl = *(const uint4*)(Bl + b_off);

    for (int kb = 0; kb < KB; kb++) {
        const int buf = kb & 1;
        uint32_t* sbase = smem + buf * STAGE_WORDS;

        // ---- STS: A split hi+lo (pairs even-k-first); B hi/lo raw
        {
            uint4 hh, ll;
            float ra, rb;
            hh.x = pack_hi(u0.x, u0.y, ra, rb); ll.x = pack_bf2(ra, rb);
            hh.y = pack_hi(u0.z, u0.w, ra, rb); ll.y = pack_bf2(ra, rb);
            hh.z = pack_hi(u1.x, u1.y, ra, rb); ll.z = pack_bf2(ra, rb);
            hh.w = pack_hi(u1.z, u1.w, ra, rb); ll.w = pack_bf2(ra, rb);
            *(uint4*)(sbase + offA)            = hh;
            *(uint4*)(sbase + offA + A_WORDS)  = ll;
            *(uint4*)(sbase + offBh)           = wh;
            *(uint4*)(sbase + offBh + B_WORDS) = wl;
        }
        __syncthreads();

        // ---- prefetch next epoch (overlaps compute below)
        if (kb + 1 < KB) {
            const float* pan = pa + (kb + 1) * BK;
            u0 = *(const float4*)(pan);
            u1 = *(const float4*)(pan + 4);
            const size_t bo = b_off + (size_t)(kb + 1) * 8 * NDIM;
            wh = *(const uint4*)(Bh + bo);
            wl = *(const uint4*)(Bl + bo);
        }

        // ---- compute: Ah*(Bh,Bl) then Al*Bh; 48 MMAs/warp
        const uint32_t* st  = smem + buf * STAGE_WORDS;
        const uint32_t* sBh = st + 2 * A_WORDS;
        const uint32_t* sBl = sBh + B_WORDS;
        uint32_t a[4][4], b0[4][2], b1[4][2];
#pragma unroll
        for (int nt = 0; nt < 4; nt++) {
            const uint32_t* p = sBh + lc * SB_PITCH + wn * 32 + nt * 8 + lr;
            b0[nt][0] = p[0];
            b0[nt][1] = p[4 * SB_PITCH];
            const uint32_t* q = sBl + lc * SB_PITCH + wn * 32 + nt * 8 + lr;
            b1[nt][0] = q[0];
            b1[nt][1] = q[4 * SB_PITCH];
        }
#pragma unroll
        for (int mt = 0; mt < 4; mt++) {               // Ah frags
            const uint32_t* p = st + (wm * 64 + mt * 16 + lr) * SA_PITCH + lc;
            a[mt][0] = p[0];
            a[mt][1] = p[8 * SA_PITCH];
            a[mt][2] = p[4];
            a[mt][3] = p[8 * SA_PITCH + 4];
        }
#pragma unroll
        for (int mt = 0; mt < 4; mt++)
#pragma unroll
            for (int nt = 0; nt < 4; nt++)
                mma_bf16(c[mt][nt], a[mt], b0[nt]);    // Ah*Bh
#pragma unroll
        for (int mt = 0; mt < 4; mt++)
#pragma unroll
            for (int nt = 0; nt < 4; nt++)
                mma_bf16(c[mt][nt], a[mt], b1[nt]);    // Ah*Bl
#pragma unroll
        for (int mt = 0; mt < 4; mt++) {               // Al frags (reuse regs)
            const uint32_t* p = st + A_WORDS + (wm * 64 + mt * 16 + lr) * SA_PITCH + lc;
            a[mt][0] = p[0];
            a[mt][1] = p[8 * SA_PITCH];
            a[mt][2] = p[4];
            a[mt][3] = p[8 * SA_PITCH + 4];
        }
#pragma unroll
        for (int mt = 0; mt < 4; mt++)
#pragma unroll
            for (int nt = 0; nt < 4; nt++)
                mma_bf16(c[mt][nt], a[mt], b0[nt]);    // Al*Bh
    }

    // ---- epilogue: bias (+GELU) + rowmap scatter
    const int lc2 = (lane & 3) * 2;
    const float* pbias = bias + (size_t)e * NDIM + n0 + wn * 32;
    float2 bv2[4];
#pragma unroll
    for (int nt = 0; nt < 4; nt++)
        bv2[nt] = *(const float2*)(pbias + nt * 8 + lc2);

#pragma unroll
    for (int mt = 0; mt < 4; mt++) {
#pragma unroll
        for (int half = 0; half < 2; half++) {
            const int gmr = m0 + wm * 64 + mt * 16 + half * 8 + lr;
            if (gmr >= cnt) continue;
            const int r = g_rowmap[e * CAP + gmr];
            float* pr = Cout + (size_t)r * NDIM + n0 + wn * 32;
#pragma unroll
            for (int nt = 0; nt < 4; nt++) {
                float x0 = c[mt][nt][half * 2 + 0] + bv2[nt].x;
                float x1 = c[mt][nt][half * 2 + 1] + bv2[nt].y;
                if (DO_GELU) { x0 = gelu_exact(x0); x1 = gelu_exact(x1); }
                *(float2*)(pr + nt * 8 + lc2) = make_float2(x0, x1);
            }
        }
    }
}

__global__ __launch_bounds__(256) void fc1_mma_kernel(
    const float* __restrict__ x, const float* __restrict__ b1) {
    gemm_mma_body<DIM, HID, true, true>(x, g_W1h, g_W1l, b1, g_h);
}
__global__ __launch_bounds__(256) void fc2_mma_kernel(const float* __restrict__ b2) {
    gemm_mma_body<HID, DIM, false, false>(g_h, g_W2h, g_W2l, b2, g_y);
}

// ------------------------------------------------------------- combine
__global__ __launch_bounds__(256) void combine_kernel(float* __restrict__ out) {
    const int t = blockIdx.x;
    const int d = threadIdx.x * 4;
    const float w0 = g_topw[2 * t];
    const float w1 = g_topw[2 * t + 1];
    const float4 y0 = *(const float4*)&g_y[(size_t)(2 * t) * DIM + d];
    const float4 y1 = *(const float4*)&g_y[(size_t)(2 * t + 1) * DIM + d];
    float4 o;
    o.x = w0 * y0.x + w1 * y1.x;
    o.y = w0 * y0.y + w1 * y1.y;
    o.z = w0 * y0.z + w1 * y1.z;
    o.w = w0 * y0.w + w1 * y1.w;
    *(float4*)(out + (size_t)t * DIM + d) = o;
}

// ------------------------------------------------------------- launch
extern "C" void kernel_launch(void* const* d_in, const int* in_sizes, int n_in,
                              void* d_out, int out_size) {
    const float* x  = (const float*)d_in[0];
    const float* Wr = (const float*)d_in[1];
    const float* W1 = (const float*)d_in[2];
    const float* b1 = (const float*)d_in[3];
    const float* W2 = (const float*)d_in[4];
    const float* b2 = (const float*)d_in[5];
    float* out = (float*)d_out;
    (void)in_sizes; (void)n_in; (void)out_size;

    zero_cnt_kernel<<<1, 32>>>();
    router_kernel<<<TOKENS, 256>>>(x, Wr);
    split_w1_kernel<<<NUM_E * (DIM / 2) * (HID / 4) / 256, 256>>>(W1);
    split_w2_kernel<<<NUM_E * (HID / 2) * (DIM / 4) / 256, 256>>>(W2);
    fc1_mma_kernel<<<dim3(CAP / BM, HID / BN, NUM_E), 256, SMEM_GEMM>>>(x, b1);
    fc2_mma_kernel<<<dim3(CAP / BM, DIM / BN, NUM_E), 256, SMEM_GEMM>>>(b2);
    combine_kernel<<<TOKENS, 256>>>(out);
}